// round 1
// baseline (speedup 1.0000x reference)
#include <cuda_runtime.h>
#include <math.h>

#define BATCH 16
#define CIN   256
#define HW    4096      // 64*64
#define DOWN  1024      // 32*32
#define C8    32
#define C2    128
#define MCONV 192       // 32 + 32 + 128

// ---------------- scratch (device globals; no allocation allowed) ----------------
__device__ float g_w   [MCONV * CIN];          // packed conv weights
__device__ float g_bias[MCONV];
__device__ float g_q   [BATCH * C8 * HW];      // 8 MB   query conv  [b][32][4096]
__device__ float g_kc  [BATCH * C8 * HW];      // 8 MB   key conv full-res
__device__ float g_vc  [BATCH * C2 * HW];      // 32 MB  val conv full-res
__device__ float g_kp  [BATCH * C8 * DOWN];    // 2 MB   pooled key  [b][32][32][32]
__device__ float g_vp  [BATCH * C2 * DOWN];    // 8 MB   pooled val  [b][128][32][32]
__device__ float g_attn[BATCH * HW * DOWN];    // 268 MB raw attention logits
__device__ float g_cmax [BATCH * DOWN];        // per-column max
__device__ float g_csumr[BATCH * DOWN];        // per-column 1/sum
__device__ float g_app [BATCH * HW * C2];      // 32 MB  applied [b][4096][128]

// ---------------- K0: pack the three conv weights into one [192,256] matrix ------
__global__ void k_pack(const float* __restrict__ qw, const float* __restrict__ qb,
                       const float* __restrict__ kw, const float* __restrict__ kb,
                       const float* __restrict__ vw, const float* __restrict__ vb) {
    int i = blockIdx.x * 256 + threadIdx.x;
    if (i < MCONV * CIN) {
        int r = i >> 8, c = i & 255;
        float v;
        if (r < 32)      v = qw[r * CIN + c];
        else if (r < 64) v = kw[(r - 32) * CIN + c];
        else             v = vw[(r - 64) * CIN + c];
        g_w[i] = v;
    }
    if (i < MCONV) {
        g_bias[i] = (i < 32) ? qb[i] : (i < 64) ? kb[i - 32] : vb[i - 64];
    }
}

// ---------------- K1: fused q/k/v 1x1 convs = [192,256] @ [256,4096] per batch ---
// 64x64 tile, BK=16, 4x4 per thread.
__global__ __launch_bounds__(256) void k_conv(const float* __restrict__ x) {
    const int b  = blockIdx.z;
    const int m0 = blockIdx.y * 64;
    const int n0 = blockIdx.x * 64;
    const float* B = x + (size_t)b * CIN * HW;

    __shared__ float As[16][68];   // transposed A chunk [k][m], padded
    __shared__ float Bs[16][64];

    const int tid = threadIdx.x;
    const int tx = tid & 15, ty = tid >> 4;
    const int arow = tid >> 2, acol = (tid & 3) * 4;   // A: 64 rows x 16 k
    const int brow = tid >> 4, bcol = (tid & 15) * 4;  // B: 16 k x 64 n

    float acc[4][4] = {};

    for (int k0 = 0; k0 < CIN; k0 += 16) {
        float4 a4 = *(const float4*)&g_w[(m0 + arow) * CIN + k0 + acol];
        As[acol + 0][arow] = a4.x;
        As[acol + 1][arow] = a4.y;
        As[acol + 2][arow] = a4.z;
        As[acol + 3][arow] = a4.w;
        *(float4*)&Bs[brow][bcol] =
            *(const float4*)&B[(size_t)(k0 + brow) * HW + n0 + bcol];
        __syncthreads();
        #pragma unroll
        for (int k = 0; k < 16; k++) {
            float a[4], bb[4];
            #pragma unroll
            for (int i = 0; i < 4; i++) a[i]  = As[k][ty * 4 + i];
            #pragma unroll
            for (int j = 0; j < 4; j++) bb[j] = Bs[k][tx * 4 + j];
            #pragma unroll
            for (int i = 0; i < 4; i++)
                #pragma unroll
                for (int j = 0; j < 4; j++)
                    acc[i][j] += a[i] * bb[j];
        }
        __syncthreads();
    }

    #pragma unroll
    for (int i = 0; i < 4; i++) {
        int m = m0 + ty * 4 + i;
        float bias = g_bias[m];
        float* dst;
        if (m < 32)      dst = g_q  + ((size_t)b * C8 + m)        * HW;
        else if (m < 64) dst = g_kc + ((size_t)b * C8 + (m - 32)) * HW;
        else             dst = g_vc + ((size_t)b * C2 + (m - 64)) * HW;
        float4 o;
        o.x = acc[i][0] + bias; o.y = acc[i][1] + bias;
        o.z = acc[i][2] + bias; o.w = acc[i][3] + bias;
        *(float4*)&dst[n0 + tx * 4] = o;
    }
}

// ---------------- K2: 2x2 max pool for key and value convs -----------------------
__global__ void k_pool() {
    int i = blockIdx.x * 256 + threadIdx.x;     // BATCH*(C8+C2)*DOWN elements
    if (i >= BATCH * (C8 + C2) * DOWN) return;
    int b  = i / ((C8 + C2) * DOWN);
    int r  = i % ((C8 + C2) * DOWN);
    int ch = r / DOWN;
    int p  = r % DOWN;
    int ph = p >> 5, pw = p & 31;
    const float* src; float* dst;
    if (ch < C8) {
        src = g_kc + ((size_t)b * C8 + ch) * HW;
        dst = g_kp + ((size_t)b * C8 + ch) * DOWN;
    } else {
        ch -= C8;
        src = g_vc + ((size_t)b * C2 + ch) * HW;
        dst = g_vp + ((size_t)b * C2 + ch) * DOWN;
    }
    int base = (ph * 2) * 64 + pw * 2;
    float v0 = src[base], v1 = src[base + 1];
    float v2 = src[base + 64], v3 = src[base + 65];
    dst[p] = fmaxf(fmaxf(v0, v1), fmaxf(v2, v3));
}

// ---------------- K3a: attn[l,j] = Q[l,:] . Kmat[j,:]  (NT GEMM, K=32) -----------
__global__ __launch_bounds__(256) void k_attn() {
    const int b  = blockIdx.z;
    const int l0 = blockIdx.y * 64;
    const int j0 = blockIdx.x * 64;

    const float* Q  = g_q  + (size_t)b * (C8 * HW);    // viewed [4096][32]
    const float* Km = g_kp + (size_t)b * (C8 * DOWN);  // viewed [1024][32]

    __shared__ float Qs[32][68];   // [d][l]
    __shared__ float Ks[32][68];   // [d][j]

    const int tid = threadIdx.x;
    const int tx = tid & 15, ty = tid >> 4;
    const int lr = tid >> 3, lc = (tid & 7) * 4;       // 32 rows per pass, float4

    {
        float4 a = *(const float4*)&Q[(size_t)(l0 + lr) * 32 + lc];
        Qs[lc + 0][lr] = a.x; Qs[lc + 1][lr] = a.y;
        Qs[lc + 2][lr] = a.z; Qs[lc + 3][lr] = a.w;
        float4 a2 = *(const float4*)&Q[(size_t)(l0 + lr + 32) * 32 + lc];
        Qs[lc + 0][lr + 32] = a2.x; Qs[lc + 1][lr + 32] = a2.y;
        Qs[lc + 2][lr + 32] = a2.z; Qs[lc + 3][lr + 32] = a2.w;
        float4 k4 = *(const float4*)&Km[(size_t)(j0 + lr) * 32 + lc];
        Ks[lc + 0][lr] = k4.x; Ks[lc + 1][lr] = k4.y;
        Ks[lc + 2][lr] = k4.z; Ks[lc + 3][lr] = k4.w;
        float4 k5 = *(const float4*)&Km[(size_t)(j0 + lr + 32) * 32 + lc];
        Ks[lc + 0][lr + 32] = k5.x; Ks[lc + 1][lr + 32] = k5.y;
        Ks[lc + 2][lr + 32] = k5.z; Ks[lc + 3][lr + 32] = k5.w;
    }
    __syncthreads();

    float acc[4][4] = {};
    #pragma unroll
    for (int d = 0; d < 32; d++) {
        float a[4], bb[4];
        #pragma unroll
        for (int i = 0; i < 4; i++) a[i]  = Qs[d][ty * 4 + i];
        #pragma unroll
        for (int j = 0; j < 4; j++) bb[j] = Ks[d][tx * 4 + j];
        #pragma unroll
        for (int i = 0; i < 4; i++)
            #pragma unroll
            for (int j = 0; j < 4; j++)
                acc[i][j] += a[i] * bb[j];
    }

    float* C = g_attn + ((size_t)b * HW + l0) * DOWN + j0;
    #pragma unroll
    for (int i = 0; i < 4; i++) {
        float4 o;
        o.x = acc[i][0]; o.y = acc[i][1]; o.z = acc[i][2]; o.w = acc[i][3];
        *(float4*)&C[(size_t)(ty * 4 + i) * DOWN + tx * 4] = o;
    }
}

// ---------------- K3b: per-column (softmax over l) max and 1/sum -----------------
__global__ void k_stats() {
    const int b = blockIdx.y;
    const int j = blockIdx.x * 256 + threadIdx.x;
    const float* A = g_attn + (size_t)b * HW * DOWN + j;
    float m = -1e30f, s = 0.f;
    #pragma unroll 4
    for (int l = 0; l < HW; l++) {
        float a = A[(size_t)l * DOWN];
        float nm = fmaxf(m, a);
        s = s * __expf(m - nm) + __expf(a - nm);
        m = nm;
    }
    g_cmax [b * DOWN + j] = m;
    g_csumr[b * DOWN + j] = 1.f / s;
}

// ---------------- K4: applied = softmax(attn) @ V  (per l-tile of 64, full C=128)-
__global__ __launch_bounds__(256) void k_apply() {
    const int b  = blockIdx.y;
    const int l0 = blockIdx.x * 64;
    const int tid = threadIdx.x;
    const int tx = tid & 31;     // c = tx*4 .. tx*4+3
    const int ty = tid >> 5;     // rows l0 + ty + 8*i

    __shared__ float Ps[64][36];
    __shared__ float Vs[32][128];

    const float* A  = g_attn + ((size_t)b * HW + l0) * DOWN;
    const float* V  = g_vp   + (size_t)b * (C2 * DOWN);  // viewed [1024][128]
    const float* cm = g_cmax  + b * DOWN;
    const float* cs = g_csumr + b * DOWN;

    float acc[8][4] = {};

    const int pr = tid >> 3;            // 0..31 (rows pr, pr+32)
    const int pc = (tid & 7) * 4;

    for (int j0 = 0; j0 < DOWN; j0 += 32) {
        // exp(attn - colmax) -> Ps
        {
            float4 mm = *(const float4*)&cm[j0 + pc];
            float4 a4 = *(const float4*)&A[(size_t)pr * DOWN + j0 + pc];
            Ps[pr][pc + 0] = __expf(a4.x - mm.x);
            Ps[pr][pc + 1] = __expf(a4.y - mm.y);
            Ps[pr][pc + 2] = __expf(a4.z - mm.z);
            Ps[pr][pc + 3] = __expf(a4.w - mm.w);
            float4 a5 = *(const float4*)&A[(size_t)(pr + 32) * DOWN + j0 + pc];
            Ps[pr + 32][pc + 0] = __expf(a5.x - mm.x);
            Ps[pr + 32][pc + 1] = __expf(a5.y - mm.y);
            Ps[pr + 32][pc + 2] = __expf(a5.z - mm.z);
            Ps[pr + 32][pc + 3] = __expf(a5.w - mm.w);
        }
        // V rows scaled by 1/colsum -> Vs
        #pragma unroll
        for (int it = 0; it < 4; it++) {
            int f  = tid + it * 256;     // 1024 float4s
            int jj = f >> 5;
            int c  = (f & 31) * 4;
            float sr = cs[j0 + jj];
            float4 v4 = *(const float4*)&V[(size_t)(j0 + jj) * C2 + c];
            float4 o; o.x = v4.x * sr; o.y = v4.y * sr; o.z = v4.z * sr; o.w = v4.w * sr;
            *(float4*)&Vs[jj][c] = o;
        }
        __syncthreads();

        #pragma unroll
        for (int jj = 0; jj < 32; jj++) {
            float4 v4 = *(const float4*)&Vs[jj][tx * 4];
            #pragma unroll
            for (int i = 0; i < 8; i++) {
                float p = Ps[ty + i * 8][jj];
                acc[i][0] += p * v4.x;
                acc[i][1] += p * v4.y;
                acc[i][2] += p * v4.z;
                acc[i][3] += p * v4.w;
            }
        }
        __syncthreads();
    }

    float* O = g_app + ((size_t)b * HW + l0) * C2;
    #pragma unroll
    for (int i = 0; i < 8; i++) {
        float4 o;
        o.x = acc[i][0]; o.y = acc[i][1]; o.z = acc[i][2]; o.w = acc[i][3];
        *(float4*)&O[(size_t)(ty + i * 8) * C2 + tx * 4] = o;
    }
}

// ---------------- K5: out = gamma * (W2 @ applied_r + b2) + x --------------------
// applied_r = applied flat buffer viewed [128][4096]; W2 [256][128]; K=128.
__global__ __launch_bounds__(256) void k_out(const float* __restrict__ w2,
                                             const float* __restrict__ b2,
                                             const float* __restrict__ gamma,
                                             const float* __restrict__ x,
                                             float* __restrict__ out) {
    const int b  = blockIdx.z;
    const int m0 = blockIdx.y * 64;
    const int n0 = blockIdx.x * 64;
    const float* B = g_app + (size_t)b * (HW * C2);   // viewed [128][4096]

    __shared__ float As[16][68];
    __shared__ float Bs[16][64];

    const int tid = threadIdx.x;
    const int tx = tid & 15, ty = tid >> 4;
    const int arow = tid >> 2, acol = (tid & 3) * 4;
    const int brow = tid >> 4, bcol = (tid & 15) * 4;

    float acc[4][4] = {};

    for (int k0 = 0; k0 < C2; k0 += 16) {
        float4 a4 = *(const float4*)&w2[(m0 + arow) * C2 + k0 + acol];
        As[acol + 0][arow] = a4.x;
        As[acol + 1][arow] = a4.y;
        As[acol + 2][arow] = a4.z;
        As[acol + 3][arow] = a4.w;
        *(float4*)&Bs[brow][bcol] =
            *(const float4*)&B[(size_t)(k0 + brow) * HW + n0 + bcol];
        __syncthreads();
        #pragma unroll
        for (int k = 0; k < 16; k++) {
            float a[4], bb[4];
            #pragma unroll
            for (int i = 0; i < 4; i++) a[i]  = As[k][ty * 4 + i];
            #pragma unroll
            for (int j = 0; j < 4; j++) bb[j] = Bs[k][tx * 4 + j];
            #pragma unroll
            for (int i = 0; i < 4; i++)
                #pragma unroll
                for (int j = 0; j < 4; j++)
                    acc[i][j] += a[i] * bb[j];
        }
        __syncthreads();
    }

    const float g = __ldg(gamma);
    #pragma unroll
    for (int i = 0; i < 4; i++) {
        int m = m0 + ty * 4 + i;
        float bias = b2[m];
        size_t base = ((size_t)b * 256 + m) * HW + n0 + tx * 4;
        float4 xi = *(const float4*)&x[base];
        float4 o;
        o.x = g * (acc[i][0] + bias) + xi.x;
        o.y = g * (acc[i][1] + bias) + xi.y;
        o.z = g * (acc[i][2] + bias) + xi.z;
        o.w = g * (acc[i][3] + bias) + xi.w;
        *(float4*)&out[base] = o;
    }
}

// ---------------- launch ---------------------------------------------------------
extern "C" void kernel_launch(void* const* d_in, const int* in_sizes, int n_in,
                              void* d_out, int out_size) {
    const float* x  = (const float*)d_in[0];
    const float* qw = (const float*)d_in[1];
    const float* qb = (const float*)d_in[2];
    const float* kw = (const float*)d_in[3];
    const float* kb = (const float*)d_in[4];
    const float* vw = (const float*)d_in[5];
    const float* vb = (const float*)d_in[6];
    const float* w2 = (const float*)d_in[7];
    const float* b2 = (const float*)d_in[8];
    const float* gm = (const float*)d_in[9];
    float* out = (float*)d_out;

    k_pack<<<(MCONV * CIN + 255) / 256, 256>>>(qw, qb, kw, kb, vw, vb);
    k_conv<<<dim3(HW / 64, MCONV / 64, BATCH), 256>>>(x);
    k_pool<<<(BATCH * (C8 + C2) * DOWN + 255) / 256, 256>>>();
    k_attn<<<dim3(DOWN / 64, HW / 64, BATCH), 256>>>();
    k_stats<<<dim3(DOWN / 256, BATCH), 256>>>();
    k_apply<<<dim3(HW / 64, BATCH), 256>>>();
    k_out<<<dim3(HW / 64, 256 / 64, BATCH), 256>>>(w2, b2, gm, x, out);
}

// round 2
// speedup vs baseline: 1.6453x; 1.6453x over previous
#include <cuda_runtime.h>
#include <math.h>

#define BATCH 16
#define CIN   256
#define HW    4096      // 64*64
#define DOWN  1024      // 32*32
#define C8    32
#define C2    128
#define MCONV 192       // 32 + 32 + 128
#define NCHUNK 8        // l-chunks for column stats

// ---------------- scratch (device globals; no allocation allowed) ----------------
__device__ float g_w   [MCONV * CIN];
__device__ float g_bias[MCONV];
__device__ float g_q   [BATCH * C8 * HW];
__device__ float g_kc  [BATCH * C8 * HW];
__device__ float g_vc  [BATCH * C2 * HW];
__device__ float g_kp  [BATCH * C8 * DOWN];
__device__ float g_vp  [BATCH * C2 * DOWN];
__device__ float g_attn[(size_t)BATCH * HW * DOWN];   // 268 MB logits
__device__ float g_pm  [BATCH * NCHUNK * DOWN];       // partial max
__device__ float g_ps  [BATCH * NCHUNK * DOWN];       // partial sumexp
__device__ float g_cmax [BATCH * DOWN];
__device__ float g_csumr[BATCH * DOWN];
__device__ float g_app [BATCH * HW * C2];

// ---------------- K0: pack conv weights ------------------------------------------
__global__ void k_pack(const float* __restrict__ qw, const float* __restrict__ qb,
                       const float* __restrict__ kw, const float* __restrict__ kb,
                       const float* __restrict__ vw, const float* __restrict__ vb) {
    int i = blockIdx.x * 256 + threadIdx.x;
    if (i < MCONV * CIN) {
        int r = i >> 8, c = i & 255;
        float v;
        if (r < 32)      v = qw[r * CIN + c];
        else if (r < 64) v = kw[(r - 32) * CIN + c];
        else             v = vw[(r - 64) * CIN + c];
        g_w[i] = v;
    }
    if (i < MCONV)
        g_bias[i] = (i < 32) ? qb[i] : (i < 64) ? kb[i - 32] : vb[i - 64];
}

// ---------------- K1: fused q/k/v convs: [192,256]@[256,4096], tile 64x128 -------
__global__ __launch_bounds__(256) void k_conv(const float* __restrict__ x) {
    const int b  = blockIdx.z;
    const int m0 = blockIdx.y * 64;
    const int n0 = blockIdx.x * 128;
    const float* B = x + (size_t)b * CIN * HW;

    __shared__ float As[16][68];    // [k][m]
    __shared__ float Bs[16][128];

    const int tid = threadIdx.x;
    const int tx = tid & 31;        // n: tx*4
    const int ty = tid >> 5;        // m: ty*8 .. +7
    const int arow = tid >> 2, acol = (tid & 3) * 4;

    float acc[8][4] = {};

    for (int k0 = 0; k0 < CIN; k0 += 16) {
        float4 a4 = *(const float4*)&g_w[(m0 + arow) * CIN + k0 + acol];
        As[acol + 0][arow] = a4.x; As[acol + 1][arow] = a4.y;
        As[acol + 2][arow] = a4.z; As[acol + 3][arow] = a4.w;
        #pragma unroll
        for (int it = 0; it < 2; it++) {
            int idx = tid + it * 256;
            int br = idx >> 5, bc = (idx & 31) * 4;
            *(float4*)&Bs[br][bc] =
                *(const float4*)&B[(size_t)(k0 + br) * HW + n0 + bc];
        }
        __syncthreads();
        #pragma unroll
        for (int k = 0; k < 16; k++) {
            float a[8], bb[4];
            *(float4*)&a[0] = *(const float4*)&As[k][ty * 8];
            *(float4*)&a[4] = *(const float4*)&As[k][ty * 8 + 4];
            *(float4*)&bb[0] = *(const float4*)&Bs[k][tx * 4];
            #pragma unroll
            for (int i = 0; i < 8; i++)
                #pragma unroll
                for (int j = 0; j < 4; j++)
                    acc[i][j] += a[i] * bb[j];
        }
        __syncthreads();
    }

    #pragma unroll
    for (int i = 0; i < 8; i++) {
        int m = m0 + ty * 8 + i;
        float bias = g_bias[m];
        float* dst;
        if (m < 32)      dst = g_q  + ((size_t)b * C8 + m)        * HW;
        else if (m < 64) dst = g_kc + ((size_t)b * C8 + (m - 32)) * HW;
        else             dst = g_vc + ((size_t)b * C2 + (m - 64)) * HW;
        float4 o;
        o.x = acc[i][0] + bias; o.y = acc[i][1] + bias;
        o.z = acc[i][2] + bias; o.w = acc[i][3] + bias;
        *(float4*)&dst[n0 + tx * 4] = o;
    }
}

// ---------------- K2: 2x2 max pool -----------------------------------------------
__global__ void k_pool() {
    int i = blockIdx.x * 256 + threadIdx.x;
    if (i >= BATCH * (C8 + C2) * DOWN) return;
    int b  = i / ((C8 + C2) * DOWN);
    int r  = i % ((C8 + C2) * DOWN);
    int ch = r / DOWN;
    int p  = r % DOWN;
    int ph = p >> 5, pw = p & 31;
    const float* src; float* dst;
    if (ch < C8) {
        src = g_kc + ((size_t)b * C8 + ch) * HW;
        dst = g_kp + ((size_t)b * C8 + ch) * DOWN;
    } else {
        ch -= C8;
        src = g_vc + ((size_t)b * C2 + ch) * HW;
        dst = g_vp + ((size_t)b * C2 + ch) * DOWN;
    }
    int base = (ph * 2) * 64 + pw * 2;
    float v0 = src[base], v1 = src[base + 1];
    float v2 = src[base + 64], v3 = src[base + 65];
    dst[p] = fmaxf(fmaxf(v0, v1), fmaxf(v2, v3));
}

// ---------------- K3a: attn = Q @ K^T, tile 64l x 128j, K=32 ---------------------
__global__ __launch_bounds__(256) void k_attn() {
    const int b  = blockIdx.z;
    const int l0 = blockIdx.y * 64;
    const int j0 = blockIdx.x * 128;

    const float* Q  = g_q  + (size_t)b * (C8 * HW);    // [4096][32]
    const float* Km = g_kp + (size_t)b * (C8 * DOWN);  // [1024][32]

    __shared__ float Qs[32][68];    // [d][l]
    __shared__ float Ks[32][132];   // [d][j]

    const int tid = threadIdx.x;
    const int tx = tid & 31;        // j: tx*4
    const int ty = tid >> 5;        // l: ty*8 .. +7

    #pragma unroll
    for (int it = 0; it < 2; it++) {
        int idx = tid + it * 256;
        int lr = idx >> 3, lc = (idx & 7) * 4;
        float4 a = *(const float4*)&Q[(size_t)(l0 + lr) * 32 + lc];
        Qs[lc + 0][lr] = a.x; Qs[lc + 1][lr] = a.y;
        Qs[lc + 2][lr] = a.z; Qs[lc + 3][lr] = a.w;
    }
    #pragma unroll
    for (int it = 0; it < 4; it++) {
        int idx = tid + it * 256;
        int jr = idx >> 3, jc = (idx & 7) * 4;
        float4 k4 = *(const float4*)&Km[(size_t)(j0 + jr) * 32 + jc];
        Ks[jc + 0][jr] = k4.x; Ks[jc + 1][jr] = k4.y;
        Ks[jc + 2][jr] = k4.z; Ks[jc + 3][jr] = k4.w;
    }
    __syncthreads();

    float acc[8][4] = {};
    #pragma unroll
    for (int d = 0; d < 32; d++) {
        float a[8], bb[4];
        *(float4*)&a[0] = *(const float4*)&Qs[d][ty * 8];
        *(float4*)&a[4] = *(const float4*)&Qs[d][ty * 8 + 4];
        *(float4*)&bb[0] = *(const float4*)&Ks[d][tx * 4];
        #pragma unroll
        for (int i = 0; i < 8; i++)
            #pragma unroll
            for (int j = 0; j < 4; j++)
                acc[i][j] += a[i] * bb[j];
    }

    float* C = g_attn + ((size_t)b * HW + l0) * DOWN + j0;
    #pragma unroll
    for (int i = 0; i < 8; i++) {
        float4 o;
        o.x = acc[i][0]; o.y = acc[i][1]; o.z = acc[i][2]; o.w = acc[i][3];
        *(float4*)&C[(size_t)(ty * 8 + i) * DOWN + tx * 4] = o;
    }
}

// ---------------- K3b: per-column partial max / sumexp over l-chunks -------------
__global__ void k_stats1() {
    const int b  = blockIdx.z;
    const int ck = blockIdx.y;
    const int j  = blockIdx.x * 256 + threadIdx.x;
    const int lsz = HW / NCHUNK;                    // 512
    const float* A = g_attn + (size_t)b * HW * DOWN + (size_t)ck * lsz * DOWN + j;
    float m = -1e30f, s = 0.f;
    #pragma unroll 4
    for (int l = 0; l < lsz; l++) {
        float a = A[(size_t)l * DOWN];
        float nm = fmaxf(m, a);
        s = s * __expf(m - nm) + __expf(a - nm);
        m = nm;
    }
    g_pm[(b * NCHUNK + ck) * DOWN + j] = m;
    g_ps[(b * NCHUNK + ck) * DOWN + j] = s;
}

__global__ void k_stats2() {
    const int b = blockIdx.y;
    const int j = blockIdx.x * 256 + threadIdx.x;
    float M = -1e30f;
    #pragma unroll
    for (int c = 0; c < NCHUNK; c++)
        M = fmaxf(M, g_pm[(b * NCHUNK + c) * DOWN + j]);
    float S = 0.f;
    #pragma unroll
    for (int c = 0; c < NCHUNK; c++)
        S += g_ps[(b * NCHUNK + c) * DOWN + j] * __expf(g_pm[(b * NCHUNK + c) * DOWN + j] - M);
    g_cmax [b * DOWN + j] = M;
    g_csumr[b * DOWN + j] = 1.f / S;
}

// ---------------- K4: applied = softmax(attn) @ V, tile 128l x 128c --------------
__global__ __launch_bounds__(256) void k_apply() {
    const int b  = blockIdx.y;
    const int l0 = blockIdx.x * 128;
    const int tid = threadIdx.x;
    const int tx = tid & 15;     // c: tx*8 .. +7
    const int ty = tid >> 4;     // l: ty + 16*i

    __shared__ float Ps[128][36];   // [l][jj]
    __shared__ float Vs[32][128];   // [jj][c]

    const float* A  = g_attn + ((size_t)b * HW + l0) * DOWN;
    const float* V  = g_vp   + (size_t)b * (C2 * DOWN);  // [1024][128]
    const float* cm = g_cmax  + b * DOWN;
    const float* cs = g_csumr + b * DOWN;

    float acc[8][8] = {};

    for (int j0 = 0; j0 < DOWN; j0 += 32) {
        #pragma unroll
        for (int it = 0; it < 4; it++) {
            int idx = tid + it * 256;          // 1024 float4s of Ps
            int row = idx >> 3;
            int c4  = (idx & 7) * 4;
            float4 mm = *(const float4*)&cm[j0 + c4];
            float4 a4 = *(const float4*)&A[(size_t)row * DOWN + j0 + c4];
            float4 o;
            o.x = __expf(a4.x - mm.x); o.y = __expf(a4.y - mm.y);
            o.z = __expf(a4.z - mm.z); o.w = __expf(a4.w - mm.w);
            *(float4*)&Ps[row][c4] = o;
        }
        #pragma unroll
        for (int it = 0; it < 4; it++) {
            int idx = tid + it * 256;          // 1024 float4s of Vs
            int jj = idx >> 5;
            int c  = (idx & 31) * 4;
            float sr = cs[j0 + jj];
            float4 v4 = *(const float4*)&V[(size_t)(j0 + jj) * C2 + c];
            float4 o; o.x = v4.x * sr; o.y = v4.y * sr; o.z = v4.z * sr; o.w = v4.w * sr;
            *(float4*)&Vs[jj][c] = o;
        }
        __syncthreads();

        #pragma unroll 8
        for (int jj = 0; jj < 32; jj++) {
            float v[8], p[8];
            *(float4*)&v[0] = *(const float4*)&Vs[jj][tx * 8];
            *(float4*)&v[4] = *(const float4*)&Vs[jj][tx * 8 + 4];
            #pragma unroll
            for (int i = 0; i < 8; i++) p[i] = Ps[ty + 16 * i][jj];
            #pragma unroll
            for (int i = 0; i < 8; i++)
                #pragma unroll
                for (int j = 0; j < 8; j++)
                    acc[i][j] += p[i] * v[j];
        }
        __syncthreads();
    }

    float* O = g_app + ((size_t)b * HW + l0) * C2;
    #pragma unroll
    for (int i = 0; i < 8; i++) {
        float4 o0, o1;
        o0.x = acc[i][0]; o0.y = acc[i][1]; o0.z = acc[i][2]; o0.w = acc[i][3];
        o1.x = acc[i][4]; o1.y = acc[i][5]; o1.z = acc[i][6]; o1.w = acc[i][7];
        *(float4*)&O[(size_t)(ty + 16 * i) * C2 + tx * 8]     = o0;
        *(float4*)&O[(size_t)(ty + 16 * i) * C2 + tx * 8 + 4] = o1;
    }
}

// ---------------- K5: out = gamma*(W2 @ applied_r + b2) + x, tile 64x128 ---------
__global__ __launch_bounds__(256) void k_out(const float* __restrict__ w2,
                                             const float* __restrict__ b2,
                                             const float* __restrict__ gamma,
                                             const float* __restrict__ x,
                                             float* __restrict__ out) {
    const int b  = blockIdx.z;
    const int m0 = blockIdx.y * 64;
    const int n0 = blockIdx.x * 128;
    const float* B = g_app + (size_t)b * (HW * C2);   // viewed [128][4096]

    __shared__ float As[16][68];
    __shared__ float Bs[16][128];

    const int tid = threadIdx.x;
    const int tx = tid & 31;
    const int ty = tid >> 5;
    const int arow = tid >> 2, acol = (tid & 3) * 4;

    float acc[8][4] = {};

    for (int k0 = 0; k0 < C2; k0 += 16) {
        float4 a4 = *(const float4*)&w2[(m0 + arow) * C2 + k0 + acol];
        As[acol + 0][arow] = a4.x; As[acol + 1][arow] = a4.y;
        As[acol + 2][arow] = a4.z; As[acol + 3][arow] = a4.w;
        #pragma unroll
        for (int it = 0; it < 2; it++) {
            int idx = tid + it * 256;
            int br = idx >> 5, bc = (idx & 31) * 4;
            *(float4*)&Bs[br][bc] =
                *(const float4*)&B[(size_t)(k0 + br) * HW + n0 + bc];
        }
        __syncthreads();
        #pragma unroll
        for (int k = 0; k < 16; k++) {
            float a[8], bb[4];
            *(float4*)&a[0] = *(const float4*)&As[k][ty * 8];
            *(float4*)&a[4] = *(const float4*)&As[k][ty * 8 + 4];
            *(float4*)&bb[0] = *(const float4*)&Bs[k][tx * 4];
            #pragma unroll
            for (int i = 0; i < 8; i++)
                #pragma unroll
                for (int j = 0; j < 4; j++)
                    acc[i][j] += a[i] * bb[j];
        }
        __syncthreads();
    }

    const float g = __ldg(gamma);
    #pragma unroll
    for (int i = 0; i < 8; i++) {
        int m = m0 + ty * 8 + i;
        float bias = b2[m];
        size_t base = ((size_t)b * 256 + m) * HW + n0 + tx * 4;
        float4 xi = *(const float4*)&x[base];
        float4 o;
        o.x = g * (acc[i][0] + bias) + xi.x;
        o.y = g * (acc[i][1] + bias) + xi.y;
        o.z = g * (acc[i][2] + bias) + xi.z;
        o.w = g * (acc[i][3] + bias) + xi.w;
        *(float4*)&out[base] = o;
    }
}

// ---------------- launch ---------------------------------------------------------
extern "C" void kernel_launch(void* const* d_in, const int* in_sizes, int n_in,
                              void* d_out, int out_size) {
    const float* x  = (const float*)d_in[0];
    const float* qw = (const float*)d_in[1];
    const float* qb = (const float*)d_in[2];
    const float* kw = (const float*)d_in[3];
    const float* kb = (const float*)d_in[4];
    const float* vw = (const float*)d_in[5];
    const float* vb = (const float*)d_in[6];
    const float* w2 = (const float*)d_in[7];
    const float* b2 = (const float*)d_in[8];
    const float* gm = (const float*)d_in[9];
    float* out = (float*)d_out;

    k_pack<<<(MCONV * CIN + 255) / 256, 256>>>(qw, qb, kw, kb, vw, vb);
    k_conv<<<dim3(HW / 128, MCONV / 64, BATCH), 256>>>(x);
    k_pool<<<(BATCH * (C8 + C2) * DOWN + 255) / 256, 256>>>();
    k_attn<<<dim3(DOWN / 128, HW / 64, BATCH), 256>>>();
    k_stats1<<<dim3(DOWN / 256, NCHUNK, BATCH), 256>>>();
    k_stats2<<<dim3(DOWN / 256, BATCH), 256>>>();
    k_apply<<<dim3(HW / 128, BATCH), 256>>>();
    k_out<<<dim3(HW / 128, 256 / 64, BATCH), 256>>>(w2, b2, gm, x, out);
}

// round 4
// speedup vs baseline: 2.3016x; 1.3989x over previous
#include <cuda_runtime.h>
#include <math.h>
#include <stdint.h>

#define BATCH 16
#define CIN   256
#define HW    4096      // 64*64
#define DOWN  1024      // 32*32
#define C8    32
#define C2    128
#define MCONV 192       // 32 + 32 + 128
#define NCHUNK 8        // l-chunks for column stats

// ---------------- scratch (device globals; no allocation allowed) ----------------
__device__ float g_w   [MCONV * CIN];
__device__ float g_bias[MCONV];
__device__ float g_q   [BATCH * C8 * HW];
__device__ float g_kc  [BATCH * C8 * HW];
__device__ float g_vc  [BATCH * C2 * HW];
__device__ float g_kp  [BATCH * C8 * DOWN];
__device__ float g_vp  [BATCH * C2 * DOWN];
__device__ float g_attn[(size_t)BATCH * HW * DOWN];   // 268 MB logits
__device__ float g_pm  [BATCH * NCHUNK * DOWN];
__device__ float g_ps  [BATCH * NCHUNK * DOWN];
__device__ float g_cmax [BATCH * DOWN];
__device__ float g_csumr[BATCH * DOWN];
__device__ float g_app [BATCH * HW * C2];

// ---------------- helpers --------------------------------------------------------
__device__ __forceinline__ uint32_t f2tf32(float v) {
    uint32_t r;
    asm("cvt.rna.tf32.f32 %0, %1;" : "=r"(r) : "f"(v));
    return r;
}
__device__ __forceinline__ void mma_tf32(float* d, const uint32_t* a, const uint32_t* b) {
    asm volatile(
        "mma.sync.aligned.m16n8k8.row.col.f32.tf32.tf32.f32 "
        "{%0,%1,%2,%3}, {%4,%5,%6,%7}, {%8,%9}, {%0,%1,%2,%3};"
        : "+f"(d[0]), "+f"(d[1]), "+f"(d[2]), "+f"(d[3])
        : "r"(a[0]), "r"(a[1]), "r"(a[2]), "r"(a[3]), "r"(b[0]), "r"(b[1]));
}

// ---------------- K0: pack conv weights ------------------------------------------
__global__ void k_pack(const float* __restrict__ qw, const float* __restrict__ qb,
                       const float* __restrict__ kw, const float* __restrict__ kb,
                       const float* __restrict__ vw, const float* __restrict__ vb) {
    int i = blockIdx.x * 256 + threadIdx.x;
    if (i < MCONV * CIN) {
        int r = i >> 8, c = i & 255;
        float v;
        if (r < 32)      v = qw[r * CIN + c];
        else if (r < 64) v = kw[(r - 32) * CIN + c];
        else             v = vw[(r - 64) * CIN + c];
        g_w[i] = v;
    }
    if (i < MCONV)
        g_bias[i] = (i < 32) ? qb[i] : (i < 64) ? kb[i - 32] : vb[i - 64];
}

// ---------------- K1: fused q/k/v convs: [192,256]@[256,4096], tile 64x128 -------
__global__ __launch_bounds__(256) void k_conv(const float* __restrict__ x) {
    const int b  = blockIdx.z;
    const int m0 = blockIdx.y * 64;
    const int n0 = blockIdx.x * 128;
    const float* B = x + (size_t)b * CIN * HW;

    __shared__ float As[16][68];
    __shared__ float Bs[16][128];

    const int tid = threadIdx.x;
    const int tx = tid & 31;
    const int ty = tid >> 5;
    const int arow = tid >> 2, acol = (tid & 3) * 4;

    float acc[8][4] = {};

    for (int k0 = 0; k0 < CIN; k0 += 16) {
        float4 a4 = *(const float4*)&g_w[(m0 + arow) * CIN + k0 + acol];
        As[acol + 0][arow] = a4.x; As[acol + 1][arow] = a4.y;
        As[acol + 2][arow] = a4.z; As[acol + 3][arow] = a4.w;
        #pragma unroll
        for (int it = 0; it < 2; it++) {
            int idx = tid + it * 256;
            int br = idx >> 5, bc = (idx & 31) * 4;
            *(float4*)&Bs[br][bc] =
                *(const float4*)&B[(size_t)(k0 + br) * HW + n0 + bc];
        }
        __syncthreads();
        #pragma unroll
        for (int k = 0; k < 16; k++) {
            float a[8], bb[4];
            *(float4*)&a[0] = *(const float4*)&As[k][ty * 8];
            *(float4*)&a[4] = *(const float4*)&As[k][ty * 8 + 4];
            *(float4*)&bb[0] = *(const float4*)&Bs[k][tx * 4];
            #pragma unroll
            for (int i = 0; i < 8; i++)
                #pragma unroll
                for (int j = 0; j < 4; j++)
                    acc[i][j] += a[i] * bb[j];
        }
        __syncthreads();
    }

    #pragma unroll
    for (int i = 0; i < 8; i++) {
        int m = m0 + ty * 8 + i;
        float bias = g_bias[m];
        float* dst;
        if (m < 32)      dst = g_q  + ((size_t)b * C8 + m)        * HW;
        else if (m < 64) dst = g_kc + ((size_t)b * C8 + (m - 32)) * HW;
        else             dst = g_vc + ((size_t)b * C2 + (m - 64)) * HW;
        float4 o;
        o.x = acc[i][0] + bias; o.y = acc[i][1] + bias;
        o.z = acc[i][2] + bias; o.w = acc[i][3] + bias;
        *(float4*)&dst[n0 + tx * 4] = o;
    }
}

// ---------------- K2: 2x2 max pool -----------------------------------------------
__global__ void k_pool() {
    int i = blockIdx.x * 256 + threadIdx.x;
    if (i >= BATCH * (C8 + C2) * DOWN) return;
    int b  = i / ((C8 + C2) * DOWN);
    int r  = i % ((C8 + C2) * DOWN);
    int ch = r / DOWN;
    int p  = r % DOWN;
    int ph = p >> 5, pw = p & 31;
    const float* src; float* dst;
    if (ch < C8) {
        src = g_kc + ((size_t)b * C8 + ch) * HW;
        dst = g_kp + ((size_t)b * C8 + ch) * DOWN;
    } else {
        ch -= C8;
        src = g_vc + ((size_t)b * C2 + ch) * HW;
        dst = g_vp + ((size_t)b * C2 + ch) * DOWN;
    }
    int base = (ph * 2) * 64 + pw * 2;
    float v0 = src[base], v1 = src[base + 1];
    float v2 = src[base + 64], v3 = src[base + 65];
    dst[p] = fmaxf(fmaxf(v0, v1), fmaxf(v2, v3));
}

// ---------------- K3a: attn = Q @ K^T, tile 64l x 128j, K=32 ---------------------
__global__ __launch_bounds__(256) void k_attn() {
    const int b  = blockIdx.z;
    const int l0 = blockIdx.y * 64;
    const int j0 = blockIdx.x * 128;

    const float* Q  = g_q  + (size_t)b * (C8 * HW);
    const float* Km = g_kp + (size_t)b * (C8 * DOWN);

    __shared__ float Qs[32][68];
    __shared__ float Ks[32][132];

    const int tid = threadIdx.x;
    const int tx = tid & 31;
    const int ty = tid >> 5;

    #pragma unroll
    for (int it = 0; it < 2; it++) {
        int idx = tid + it * 256;
        int lr = idx >> 3, lc = (idx & 7) * 4;
        float4 a = *(const float4*)&Q[(size_t)(l0 + lr) * 32 + lc];
        Qs[lc + 0][lr] = a.x; Qs[lc + 1][lr] = a.y;
        Qs[lc + 2][lr] = a.z; Qs[lc + 3][lr] = a.w;
    }
    #pragma unroll
    for (int it = 0; it < 4; it++) {
        int idx = tid + it * 256;
        int jr = idx >> 3, jc = (idx & 7) * 4;
        float4 k4 = *(const float4*)&Km[(size_t)(j0 + jr) * 32 + jc];
        Ks[jc + 0][jr] = k4.x; Ks[jc + 1][jr] = k4.y;
        Ks[jc + 2][jr] = k4.z; Ks[jc + 3][jr] = k4.w;
    }
    __syncthreads();

    float acc[8][4] = {};
    #pragma unroll
    for (int d = 0; d < 32; d++) {
        float a[8], bb[4];
        *(float4*)&a[0] = *(const float4*)&Qs[d][ty * 8];
        *(float4*)&a[4] = *(const float4*)&Qs[d][ty * 8 + 4];
        *(float4*)&bb[0] = *(const float4*)&Ks[d][tx * 4];
        #pragma unroll
        for (int i = 0; i < 8; i++)
            #pragma unroll
            for (int j = 0; j < 4; j++)
                acc[i][j] += a[i] * bb[j];
    }

    float* C = g_attn + ((size_t)b * HW + l0) * DOWN + j0;
    #pragma unroll
    for (int i = 0; i < 8; i++) {
        float4 o;
        o.x = acc[i][0]; o.y = acc[i][1]; o.z = acc[i][2]; o.w = acc[i][3];
        *(float4*)&C[(size_t)(ty * 8 + i) * DOWN + tx * 4] = o;
    }
}

// ---------------- K3b: per-column partial max / sumexp over l-chunks -------------
__global__ void k_stats1() {
    const int b  = blockIdx.z;
    const int ck = blockIdx.y;
    const int j  = blockIdx.x * 256 + threadIdx.x;
    const int lsz = HW / NCHUNK;
    const float* A = g_attn + (size_t)b * HW * DOWN + (size_t)ck * lsz * DOWN + j;
    float m = -1e30f, s = 0.f;
    #pragma unroll 4
    for (int l = 0; l < lsz; l++) {
        float a = A[(size_t)l * DOWN];
        float nm = fmaxf(m, a);
        s = s * __expf(m - nm) + __expf(a - nm);
        m = nm;
    }
    g_pm[(b * NCHUNK + ck) * DOWN + j] = m;
    g_ps[(b * NCHUNK + ck) * DOWN + j] = s;
}

__global__ void k_stats2() {
    const int b = blockIdx.y;
    const int j = blockIdx.x * 256 + threadIdx.x;
    float M = -1e30f;
    #pragma unroll
    for (int c = 0; c < NCHUNK; c++)
        M = fmaxf(M, g_pm[(b * NCHUNK + c) * DOWN + j]);
    float S = 0.f;
    #pragma unroll
    for (int c = 0; c < NCHUNK; c++)
        S += g_ps[(b * NCHUNK + c) * DOWN + j] * __expf(g_pm[(b * NCHUNK + c) * DOWN + j] - M);
    g_cmax [b * DOWN + j] = M;
    g_csumr[b * DOWN + j] = 1.f / S;
}

// ---------------- K4: applied = softmax(attn) @ V via mma.sync tf32 --------------
// Block 128l x 128c, 8 warps (2x4), warp tile 64x32, k-chunks of 32 over j.
__global__ __launch_bounds__(256, 2) void k_apply_mma() {
    __shared__ float sP[128][36];   // [l][j]  (A, row-major M x K)
    __shared__ float sB[128][36];   // [c][j]  (B^T: value B[k=j][n=c])

    const int b   = blockIdx.y;
    const int l0  = blockIdx.x * 128;
    const int tid = threadIdx.x;
    const int wid = tid >> 5;
    const int lane = tid & 31;
    const int qid = lane >> 2;      // 0..7
    const int qtr = lane & 3;       // 0..3
    const int wm = (wid >> 2) * 64; // warp m offset (0 or 64)
    const int wn = (wid & 3) * 32;  // warp n offset

    const float* A  = g_attn + ((size_t)b * HW + l0) * DOWN;
    const float* V  = g_vp   + (size_t)b * (C2 * DOWN);   // [1024][128]
    const float* cm = g_cmax  + b * DOWN;
    const float* cs = g_csumr + b * DOWN;

    float acc[4][4][4] = {};   // [m-atom][n-atom][reg]

    for (int j0 = 0; j0 < DOWN; j0 += 32) {
        // stage P = exp(attn - colmax), converted to tf32
        #pragma unroll
        for (int it = 0; it < 4; it++) {
            int idx = tid + it * 256;
            int l = idx >> 3, jg = (idx & 7) * 4;
            float4 mm = *(const float4*)&cm[j0 + jg];
            float4 a4 = *(const float4*)&A[(size_t)l * DOWN + j0 + jg];
            uint32_t* dp = (uint32_t*)&sP[l][jg];
            dp[0] = f2tf32(__expf(a4.x - mm.x));
            dp[1] = f2tf32(__expf(a4.y - mm.y));
            dp[2] = f2tf32(__expf(a4.z - mm.z));
            dp[3] = f2tf32(__expf(a4.w - mm.w));
        }
        // stage B[c][j] = V[j][c] * csumr[j] (transpose), tf32
        #pragma unroll
        for (int it = 0; it < 4; it++) {
            int idx = tid + it * 256;
            int c = idx & 127, j4 = idx >> 7;   // j4 in 0..7
            float4 s4 = *(const float4*)&cs[j0 + j4 * 4];
            uint32_t* dp = (uint32_t*)&sB[c][j4 * 4];
            dp[0] = f2tf32(V[(size_t)(j0 + j4 * 4 + 0) * C2 + c] * s4.x);
            dp[1] = f2tf32(V[(size_t)(j0 + j4 * 4 + 1) * C2 + c] * s4.y);
            dp[2] = f2tf32(V[(size_t)(j0 + j4 * 4 + 2) * C2 + c] * s4.z);
            dp[3] = f2tf32(V[(size_t)(j0 + j4 * 4 + 3) * C2 + c] * s4.w);
        }
        __syncthreads();

        #pragma unroll
        for (int ks = 0; ks < 4; ks++) {
            const int k0 = ks * 8;
            uint32_t af[4][4], bf[4][2];
            #pragma unroll
            for (int ma = 0; ma < 4; ma++) {
                int r = wm + ma * 16 + qid;
                af[ma][0] = __float_as_uint(sP[r    ][k0 + qtr]);
                af[ma][1] = __float_as_uint(sP[r + 8][k0 + qtr]);
                af[ma][2] = __float_as_uint(sP[r    ][k0 + qtr + 4]);
                af[ma][3] = __float_as_uint(sP[r + 8][k0 + qtr + 4]);
            }
            #pragma unroll
            for (int na = 0; na < 4; na++) {
                int c = wn + na * 8 + qid;
                bf[na][0] = __float_as_uint(sB[c][k0 + qtr]);
                bf[na][1] = __float_as_uint(sB[c][k0 + qtr + 4]);
            }
            #pragma unroll
            for (int ma = 0; ma < 4; ma++)
                #pragma unroll
                for (int na = 0; na < 4; na++)
                    mma_tf32(acc[ma][na], af[ma], bf[na]);
        }
        __syncthreads();
    }

    float* O = g_app + ((size_t)b * HW + l0) * C2;
    #pragma unroll
    for (int ma = 0; ma < 4; ma++) {
        int r = wm + ma * 16 + qid;
        #pragma unroll
        for (int na = 0; na < 4; na++) {
            int c = wn + na * 8 + 2 * qtr;
            float2 lo, hi;
            lo.x = acc[ma][na][0]; lo.y = acc[ma][na][1];
            hi.x = acc[ma][na][2]; hi.y = acc[ma][na][3];
            *(float2*)&O[(size_t)r * C2 + c]       = lo;
            *(float2*)&O[(size_t)(r + 8) * C2 + c] = hi;
        }
    }
}

// ---------------- K5: out = gamma*(W2 @ applied_r + b2) + x, tile 64x128 ---------
__global__ __launch_bounds__(256) void k_out(const float* __restrict__ w2,
                                             const float* __restrict__ b2,
                                             const float* __restrict__ gamma,
                                             const float* __restrict__ x,
                                             float* __restrict__ out) {
    const int b  = blockIdx.z;
    const int m0 = blockIdx.y * 64;
    const int n0 = blockIdx.x * 128;
    const float* B = g_app + (size_t)b * (HW * C2);   // viewed [128][4096]

    __shared__ float As[16][68];
    __shared__ float Bs[16][128];

    const int tid = threadIdx.x;
    const int tx = tid & 31;
    const int ty = tid >> 5;
    const int arow = tid >> 2, acol = (tid & 3) * 4;

    float acc[8][4] = {};

    for (int k0 = 0; k0 < C2; k0 += 16) {
        float4 a4 = *(const float4*)&w2[(m0 + arow) * C2 + k0 + acol];
        As[acol + 0][arow] = a4.x; As[acol + 1][arow] = a4.y;
        As[acol + 2][arow] = a4.z; As[acol + 3][arow] = a4.w;
        #pragma unroll
        for (int it = 0; it < 2; it++) {
            int idx = tid + it * 256;
            int br = idx >> 5, bc = (idx & 31) * 4;
            *(float4*)&Bs[br][bc] =
                *(const float4*)&B[(size_t)(k0 + br) * HW + n0 + bc];
        }
        __syncthreads();
        #pragma unroll
        for (int k = 0; k < 16; k++) {
            float a[8], bb[4];
            *(float4*)&a[0] = *(const float4*)&As[k][ty * 8];
            *(float4*)&a[4] = *(const float4*)&As[k][ty * 8 + 4];
            *(float4*)&bb[0] = *(const float4*)&Bs[k][tx * 4];
            #pragma unroll
            for (int i = 0; i < 8; i++)
                #pragma unroll
                for (int j = 0; j < 4; j++)
                    acc[i][j] += a[i] * bb[j];
        }
        __syncthreads();
    }

    const float g = __ldg(gamma);
    #pragma unroll
    for (int i = 0; i < 8; i++) {
        int m = m0 + ty * 8 + i;
        float bias = b2[m];
        size_t base = ((size_t)b * 256 + m) * HW + n0 + tx * 4;
        float4 xi = *(const float4*)&x[base];
        float4 o;
        o.x = g * (acc[i][0] + bias) + xi.x;
        o.y = g * (acc[i][1] + bias) + xi.y;
        o.z = g * (acc[i][2] + bias) + xi.z;
        o.w = g * (acc[i][3] + bias) + xi.w;
        *(float4*)&out[base] = o;
    }
}

// ---------------- launch ---------------------------------------------------------
extern "C" void kernel_launch(void* const* d_in, const int* in_sizes, int n_in,
                              void* d_out, int out_size) {
    const float* x  = (const float*)d_in[0];
    const float* qw = (const float*)d_in[1];
    const float* qb = (const float*)d_in[2];
    const float* kw = (const float*)d_in[3];
    const float* kb = (const float*)d_in[4];
    const float* vw = (const float*)d_in[5];
    const float* vb = (const float*)d_in[6];
    const float* w2 = (const float*)d_in[7];
    const float* b2 = (const float*)d_in[8];
    const float* gm = (const float*)d_in[9];
    float* out = (float*)d_out;

    k_pack<<<(MCONV * CIN + 255) / 256, 256>>>(qw, qb, kw, kb, vw, vb);
    k_conv<<<dim3(HW / 128, MCONV / 64, BATCH), 256>>>(x);
    k_pool<<<(BATCH * (C8 + C2) * DOWN + 255) / 256, 256>>>();
    k_attn<<<dim3(DOWN / 128, HW / 64, BATCH), 256>>>();
    k_stats1<<<dim3(DOWN / 256, NCHUNK, BATCH), 256>>>();
    k_stats2<<<dim3(DOWN / 256, BATCH), 256>>>();
    k_apply_mma<<<dim3(HW / 128, BATCH), 256>>>();
    k_out<<<dim3(HW / 128, 256 / 64, BATCH), 256>>>(w2, b2, gm, x, out);
}

// round 5
// speedup vs baseline: 2.7931x; 1.2136x over previous
#include <cuda_runtime.h>
#include <math.h>
#include <stdint.h>

#define BATCH 16
#define CIN   256
#define HW    4096      // 64*64
#define DOWN  1024      // 32*32
#define C8    32
#define C2    128
#define MCONV 192       // 32 + 32 + 128
#define NCHUNK 8        // l-chunks for column stats

// ---------------- scratch (device globals; no allocation allowed) ----------------
__device__ float g_w   [MCONV * CIN];
__device__ float g_bias[MCONV];
__device__ float g_q   [BATCH * C8 * HW];
__device__ float g_kc  [BATCH * C8 * HW];
__device__ float g_vc  [BATCH * C2 * HW];
__device__ float g_kp  [BATCH * C8 * DOWN];
__device__ float g_vp  [BATCH * C2 * DOWN];
__device__ float g_attn[(size_t)BATCH * HW * DOWN];   // 268 MB logits
__device__ float g_pm  [BATCH * NCHUNK * DOWN];
__device__ float g_ps  [BATCH * NCHUNK * DOWN];
__device__ float g_cmax [BATCH * DOWN];
__device__ float g_csumr[BATCH * DOWN];
__device__ float g_app [BATCH * HW * C2];

// ---------------- helpers --------------------------------------------------------
__device__ __forceinline__ uint32_t f2tf32(float v) {
    uint32_t r;
    asm("cvt.rna.tf32.f32 %0, %1;" : "=r"(r) : "f"(v));
    return r;
}
__device__ __forceinline__ void mma_tf32(float* d, const uint32_t* a, const uint32_t* b) {
    asm volatile(
        "mma.sync.aligned.m16n8k8.row.col.f32.tf32.tf32.f32 "
        "{%0,%1,%2,%3}, {%4,%5,%6,%7}, {%8,%9}, {%0,%1,%2,%3};"
        : "+f"(d[0]), "+f"(d[1]), "+f"(d[2]), "+f"(d[3])
        : "r"(a[0]), "r"(a[1]), "r"(a[2]), "r"(a[3]), "r"(b[0]), "r"(b[1]));
}

// ---------------- K0: pack conv weights ------------------------------------------
__global__ void k_pack(const float* __restrict__ qw, const float* __restrict__ qb,
                       const float* __restrict__ kw, const float* __restrict__ kb,
                       const float* __restrict__ vw, const float* __restrict__ vb) {
    int i = blockIdx.x * 256 + threadIdx.x;
    if (i < MCONV * CIN) {
        int r = i >> 8, c = i & 255;
        float v;
        if (r < 32)      v = qw[r * CIN + c];
        else if (r < 64) v = kw[(r - 32) * CIN + c];
        else             v = vw[(r - 64) * CIN + c];
        g_w[i] = v;
    }
    if (i < MCONV)
        g_bias[i] = (i < 32) ? qb[i] : (i < 64) ? kb[i - 32] : vb[i - 64];
}

// ---------------- K1: fused q/k/v convs via mma tf32 -----------------------------
// C[192,4096] = W[192,256] @ X[256,4096] per batch. Block 64m x 128n, k-chunks 32.
__global__ __launch_bounds__(256) void k_conv_mma(const float* __restrict__ x) {
    __shared__ float sA[64][36];    // W tile [m][k]
    __shared__ float sB[32][136];   // X tile [k][n], pad 136 -> conflict-free frags

    const int b  = blockIdx.z;
    const int m0 = blockIdx.y * 64;
    const int n0 = blockIdx.x * 128;
    const float* X = x + (size_t)b * CIN * HW;

    const int tid  = threadIdx.x;
    const int wid  = tid >> 5;
    const int lane = tid & 31;
    const int qid  = lane >> 2;
    const int qtr  = lane & 3;
    const int wm   = (wid >> 2) * 32;   // 0 or 32
    const int wn   = (wid & 3) * 32;    // 0,32,64,96

    float acc[2][4][4] = {};

    for (int k0 = 0; k0 < CIN; k0 += 32) {
        // stage A: 64x32 = 512 float4 -> 2 per thread (cvt to tf32)
        #pragma unroll
        for (int it = 0; it < 2; it++) {
            int f = tid + it * 256;
            int m = f >> 3, k4 = (f & 7) * 4;
            float4 a4 = *(const float4*)&g_w[(m0 + m) * CIN + k0 + k4];
            uint32_t* dp = (uint32_t*)&sA[m][k4];
            dp[0] = f2tf32(a4.x); dp[1] = f2tf32(a4.y);
            dp[2] = f2tf32(a4.z); dp[3] = f2tf32(a4.w);
        }
        // stage B: 32x128 = 1024 float4 -> 4 per thread
        #pragma unroll
        for (int it = 0; it < 4; it++) {
            int f = tid + it * 256;
            int kk = f >> 5, n4 = (f & 31) * 4;
            float4 b4 = *(const float4*)&X[(size_t)(k0 + kk) * HW + n0 + n4];
            uint32_t* dp = (uint32_t*)&sB[kk][n4];
            dp[0] = f2tf32(b4.x); dp[1] = f2tf32(b4.y);
            dp[2] = f2tf32(b4.z); dp[3] = f2tf32(b4.w);
        }
        __syncthreads();

        #pragma unroll
        for (int ks = 0; ks < 4; ks++) {
            const int kk = ks * 8;
            uint32_t af[2][4], bf[4][2];
            #pragma unroll
            for (int ma = 0; ma < 2; ma++) {
                int r = wm + ma * 16 + qid;
                af[ma][0] = __float_as_uint(sA[r    ][kk + qtr]);
                af[ma][1] = __float_as_uint(sA[r + 8][kk + qtr]);
                af[ma][2] = __float_as_uint(sA[r    ][kk + qtr + 4]);
                af[ma][3] = __float_as_uint(sA[r + 8][kk + qtr + 4]);
            }
            #pragma unroll
            for (int na = 0; na < 4; na++) {
                int c = wn + na * 8 + qid;
                bf[na][0] = __float_as_uint(sB[kk + qtr    ][c]);
                bf[na][1] = __float_as_uint(sB[kk + qtr + 4][c]);
            }
            #pragma unroll
            for (int ma = 0; ma < 2; ma++)
                #pragma unroll
                for (int na = 0; na < 4; na++)
                    mma_tf32(acc[ma][na], af[ma], bf[na]);
        }
        __syncthreads();
    }

    // epilogue: route rows to g_q / g_kc / g_vc (+bias)
    #pragma unroll
    for (int ma = 0; ma < 2; ma++) {
        #pragma unroll
        for (int half = 0; half < 2; half++) {
            int m = m0 + wm + ma * 16 + qid + half * 8;
            float bias = g_bias[m];
            float* dst;
            if (m < 32)      dst = g_q  + ((size_t)b * C8 + m)        * HW;
            else if (m < 64) dst = g_kc + ((size_t)b * C8 + (m - 32)) * HW;
            else             dst = g_vc + ((size_t)b * C2 + (m - 64)) * HW;
            #pragma unroll
            for (int na = 0; na < 4; na++) {
                int c = n0 + wn + na * 8 + 2 * qtr;
                float2 o;
                o.x = acc[ma][na][half * 2 + 0] + bias;
                o.y = acc[ma][na][half * 2 + 1] + bias;
                *(float2*)&dst[c] = o;
            }
        }
    }
}

// ---------------- K2: 2x2 max pool -----------------------------------------------
__global__ void k_pool() {
    int i = blockIdx.x * 256 + threadIdx.x;
    if (i >= BATCH * (C8 + C2) * DOWN) return;
    int b  = i / ((C8 + C2) * DOWN);
    int r  = i % ((C8 + C2) * DOWN);
    int ch = r / DOWN;
    int p  = r % DOWN;
    int ph = p >> 5, pw = p & 31;
    const float* src; float* dst;
    if (ch < C8) {
        src = g_kc + ((size_t)b * C8 + ch) * HW;
        dst = g_kp + ((size_t)b * C8 + ch) * DOWN;
    } else {
        ch -= C8;
        src = g_vc + ((size_t)b * C2 + ch) * HW;
        dst = g_vp + ((size_t)b * C2 + ch) * DOWN;
    }
    int base = (ph * 2) * 64 + pw * 2;
    float v0 = src[base], v1 = src[base + 1];
    float v2 = src[base + 64], v3 = src[base + 65];
    dst[p] = fmaxf(fmaxf(v0, v1), fmaxf(v2, v3));
}

// ---------------- K3a: attn = Q @ K^T, tile 64l x 128j, K=32 (fp32) --------------
__global__ __launch_bounds__(256) void k_attn() {
    const int b  = blockIdx.z;
    const int l0 = blockIdx.y * 64;
    const int j0 = blockIdx.x * 128;

    const float* Q  = g_q  + (size_t)b * (C8 * HW);
    const float* Km = g_kp + (size_t)b * (C8 * DOWN);

    __shared__ float Qs[32][68];
    __shared__ float Ks[32][132];

    const int tid = threadIdx.x;
    const int tx = tid & 31;
    const int ty = tid >> 5;

    #pragma unroll
    for (int it = 0; it < 2; it++) {
        int idx = tid + it * 256;
        int lr = idx >> 3, lc = (idx & 7) * 4;
        float4 a = *(const float4*)&Q[(size_t)(l0 + lr) * 32 + lc];
        Qs[lc + 0][lr] = a.x; Qs[lc + 1][lr] = a.y;
        Qs[lc + 2][lr] = a.z; Qs[lc + 3][lr] = a.w;
    }
    #pragma unroll
    for (int it = 0; it < 4; it++) {
        int idx = tid + it * 256;
        int jr = idx >> 3, jc = (idx & 7) * 4;
        float4 k4 = *(const float4*)&Km[(size_t)(j0 + jr) * 32 + jc];
        Ks[jc + 0][jr] = k4.x; Ks[jc + 1][jr] = k4.y;
        Ks[jc + 2][jr] = k4.z; Ks[jc + 3][jr] = k4.w;
    }
    __syncthreads();

    float acc[8][4] = {};
    #pragma unroll
    for (int d = 0; d < 32; d++) {
        float a[8], bb[4];
        *(float4*)&a[0] = *(const float4*)&Qs[d][ty * 8];
        *(float4*)&a[4] = *(const float4*)&Qs[d][ty * 8 + 4];
        *(float4*)&bb[0] = *(const float4*)&Ks[d][tx * 4];
        #pragma unroll
        for (int i = 0; i < 8; i++)
            #pragma unroll
            for (int j = 0; j < 4; j++)
                acc[i][j] += a[i] * bb[j];
    }

    float* C = g_attn + ((size_t)b * HW + l0) * DOWN + j0;
    #pragma unroll
    for (int i = 0; i < 8; i++) {
        float4 o;
        o.x = acc[i][0]; o.y = acc[i][1]; o.z = acc[i][2]; o.w = acc[i][3];
        *(float4*)&C[(size_t)(ty * 8 + i) * DOWN + tx * 4] = o;
    }
}

// ---------------- K3b: per-column partial max / sumexp over l-chunks -------------
__global__ void k_stats1() {
    const int b  = blockIdx.z;
    const int ck = blockIdx.y;
    const int j  = blockIdx.x * 256 + threadIdx.x;
    const int lsz = HW / NCHUNK;
    const float* A = g_attn + (size_t)b * HW * DOWN + (size_t)ck * lsz * DOWN + j;
    float m = -1e30f, s = 0.f;
    #pragma unroll 4
    for (int l = 0; l < lsz; l++) {
        float a = A[(size_t)l * DOWN];
        float nm = fmaxf(m, a);
        s = s * __expf(m - nm) + __expf(a - nm);
        m = nm;
    }
    g_pm[(b * NCHUNK + ck) * DOWN + j] = m;
    g_ps[(b * NCHUNK + ck) * DOWN + j] = s;
}

__global__ void k_stats2() {
    const int b = blockIdx.y;
    const int j = blockIdx.x * 256 + threadIdx.x;
    float M = -1e30f;
    #pragma unroll
    for (int c = 0; c < NCHUNK; c++)
        M = fmaxf(M, g_pm[(b * NCHUNK + c) * DOWN + j]);
    float S = 0.f;
    #pragma unroll
    for (int c = 0; c < NCHUNK; c++)
        S += g_ps[(b * NCHUNK + c) * DOWN + j] * __expf(g_pm[(b * NCHUNK + c) * DOWN + j] - M);
    g_cmax [b * DOWN + j] = M;
    g_csumr[b * DOWN + j] = 1.f / S;
}

// ---------------- K4: applied = softmax(attn) @ V via mma.sync tf32 --------------
__global__ __launch_bounds__(256, 2) void k_apply_mma() {
    __shared__ float sP[128][36];   // [l][j]
    __shared__ float sB[128][36];   // [c][j]

    const int b   = blockIdx.y;
    const int l0  = blockIdx.x * 128;
    const int tid = threadIdx.x;
    const int wid = tid >> 5;
    const int lane = tid & 31;
    const int qid = lane >> 2;
    const int qtr = lane & 3;
    const int wm = (wid >> 2) * 64;
    const int wn = (wid & 3) * 32;

    const float* A  = g_attn + ((size_t)b * HW + l0) * DOWN;
    const float* V  = g_vp   + (size_t)b * (C2 * DOWN);
    const float* cm = g_cmax  + b * DOWN;
    const float* cs = g_csumr + b * DOWN;

    float acc[4][4][4] = {};

    for (int j0 = 0; j0 < DOWN; j0 += 32) {
        #pragma unroll
        for (int it = 0; it < 4; it++) {
            int idx = tid + it * 256;
            int l = idx >> 3, jg = (idx & 7) * 4;
            float4 mm = *(const float4*)&cm[j0 + jg];
            float4 a4 = *(const float4*)&A[(size_t)l * DOWN + j0 + jg];
            uint32_t* dp = (uint32_t*)&sP[l][jg];
            dp[0] = f2tf32(__expf(a4.x - mm.x));
            dp[1] = f2tf32(__expf(a4.y - mm.y));
            dp[2] = f2tf32(__expf(a4.z - mm.z));
            dp[3] = f2tf32(__expf(a4.w - mm.w));
        }
        #pragma unroll
        for (int it = 0; it < 4; it++) {
            int idx = tid + it * 256;
            int c = idx & 127, j4 = idx >> 7;
            float4 s4 = *(const float4*)&cs[j0 + j4 * 4];
            uint32_t* dp = (uint32_t*)&sB[c][j4 * 4];
            dp[0] = f2tf32(V[(size_t)(j0 + j4 * 4 + 0) * C2 + c] * s4.x);
            dp[1] = f2tf32(V[(size_t)(j0 + j4 * 4 + 1) * C2 + c] * s4.y);
            dp[2] = f2tf32(V[(size_t)(j0 + j4 * 4 + 2) * C2 + c] * s4.z);
            dp[3] = f2tf32(V[(size_t)(j0 + j4 * 4 + 3) * C2 + c] * s4.w);
        }
        __syncthreads();

        #pragma unroll
        for (int ks = 0; ks < 4; ks++) {
            const int k0 = ks * 8;
            uint32_t af[4][4], bf[4][2];
            #pragma unroll
            for (int ma = 0; ma < 4; ma++) {
                int r = wm + ma * 16 + qid;
                af[ma][0] = __float_as_uint(sP[r    ][k0 + qtr]);
                af[ma][1] = __float_as_uint(sP[r + 8][k0 + qtr]);
                af[ma][2] = __float_as_uint(sP[r    ][k0 + qtr + 4]);
                af[ma][3] = __float_as_uint(sP[r + 8][k0 + qtr + 4]);
            }
            #pragma unroll
            for (int na = 0; na < 4; na++) {
                int c = wn + na * 8 + qid;
                bf[na][0] = __float_as_uint(sB[c][k0 + qtr]);
                bf[na][1] = __float_as_uint(sB[c][k0 + qtr + 4]);
            }
            #pragma unroll
            for (int ma = 0; ma < 4; ma++)
                #pragma unroll
                for (int na = 0; na < 4; na++)
                    mma_tf32(acc[ma][na], af[ma], bf[na]);
        }
        __syncthreads();
    }

    float* O = g_app + ((size_t)b * HW + l0) * C2;
    #pragma unroll
    for (int ma = 0; ma < 4; ma++) {
        int r = wm + ma * 16 + qid;
        #pragma unroll
        for (int na = 0; na < 4; na++) {
            int c = wn + na * 8 + 2 * qtr;
            float2 lo, hi;
            lo.x = acc[ma][na][0]; lo.y = acc[ma][na][1];
            hi.x = acc[ma][na][2]; hi.y = acc[ma][na][3];
            *(float2*)&O[(size_t)r * C2 + c]       = lo;
            *(float2*)&O[(size_t)(r + 8) * C2 + c] = hi;
        }
    }
}

// ---------------- K5: out = gamma*(W2 @ applied_r + b2) + x via mma tf32 ---------
// C[256,4096] = W2[256,128] @ appflat[128,4096] per batch. Block 64m x 128n.
__global__ __launch_bounds__(256) void k_out_mma(const float* __restrict__ w2,
                                                 const float* __restrict__ b2,
                                                 const float* __restrict__ gamma,
                                                 const float* __restrict__ x,
                                                 float* __restrict__ out) {
    __shared__ float sA[64][36];
    __shared__ float sB[32][136];

    const int b  = blockIdx.z;
    const int m0 = blockIdx.y * 64;
    const int n0 = blockIdx.x * 128;
    const float* Bm = g_app + (size_t)b * (HW * C2);   // viewed [128][4096]

    const int tid  = threadIdx.x;
    const int wid  = tid >> 5;
    const int lane = tid & 31;
    const int qid  = lane >> 2;
    const int qtr  = lane & 3;
    const int wm   = (wid >> 2) * 32;
    const int wn   = (wid & 3) * 32;

    float acc[2][4][4] = {};

    for (int k0 = 0; k0 < C2; k0 += 32) {
        #pragma unroll
        for (int it = 0; it < 2; it++) {
            int f = tid + it * 256;
            int m = f >> 3, k4 = (f & 7) * 4;
            float4 a4 = *(const float4*)&w2[(m0 + m) * C2 + k0 + k4];
            uint32_t* dp = (uint32_t*)&sA[m][k4];
            dp[0] = f2tf32(a4.x); dp[1] = f2tf32(a4.y);
            dp[2] = f2tf32(a4.z); dp[3] = f2tf32(a4.w);
        }
        #pragma unroll
        for (int it = 0; it < 4; it++) {
            int f = tid + it * 256;
            int kk = f >> 5, n4 = (f & 31) * 4;
            float4 b4 = *(const float4*)&Bm[(size_t)(k0 + kk) * HW + n0 + n4];
            uint32_t* dp = (uint32_t*)&sB[kk][n4];
            dp[0] = f2tf32(b4.x); dp[1] = f2tf32(b4.y);
            dp[2] = f2tf32(b4.z); dp[3] = f2tf32(b4.w);
        }
        __syncthreads();

        #pragma unroll
        for (int ks = 0; ks < 4; ks++) {
            const int kk = ks * 8;
            uint32_t af[2][4], bf[4][2];
            #pragma unroll
            for (int ma = 0; ma < 2; ma++) {
                int r = wm + ma * 16 + qid;
                af[ma][0] = __float_as_uint(sA[r    ][kk + qtr]);
                af[ma][1] = __float_as_uint(sA[r + 8][kk + qtr]);
                af[ma][2] = __float_as_uint(sA[r    ][kk + qtr + 4]);
                af[ma][3] = __float_as_uint(sA[r + 8][kk + qtr + 4]);
            }
            #pragma unroll
            for (int na = 0; na < 4; na++) {
                int c = wn + na * 8 + qid;
                bf[na][0] = __float_as_uint(sB[kk + qtr    ][c]);
                bf[na][1] = __float_as_uint(sB[kk + qtr + 4][c]);
            }
            #pragma unroll
            for (int ma = 0; ma < 2; ma++)
                #pragma unroll
                for (int na = 0; na < 4; na++)
                    mma_tf32(acc[ma][na], af[ma], bf[na]);
        }
        __syncthreads();
    }

    const float g = __ldg(gamma);
    #pragma unroll
    for (int ma = 0; ma < 2; ma++) {
        #pragma unroll
        for (int half = 0; half < 2; half++) {
            int m = m0 + wm + ma * 16 + qid + half * 8;
            float bias = b2[m];
            #pragma unroll
            for (int na = 0; na < 4; na++) {
                int c = n0 + wn + na * 8 + 2 * qtr;
                size_t base = ((size_t)b * 256 + m) * HW + c;
                float2 xi = *(const float2*)&x[base];
                float2 o;
                o.x = g * (acc[ma][na][half * 2 + 0] + bias) + xi.x;
                o.y = g * (acc[ma][na][half * 2 + 1] + bias) + xi.y;
                *(float2*)&out[base] = o;
            }
        }
    }
}

// ---------------- launch ---------------------------------------------------------
extern "C" void kernel_launch(void* const* d_in, const int* in_sizes, int n_in,
                              void* d_out, int out_size) {
    const float* x  = (const float*)d_in[0];
    const float* qw = (const float*)d_in[1];
    const float* qb = (const float*)d_in[2];
    const float* kw = (const float*)d_in[3];
    const float* kb = (const float*)d_in[4];
    const float* vw = (const float*)d_in[5];
    const float* vb = (const float*)d_in[6];
    const float* w2 = (const float*)d_in[7];
    const float* b2 = (const float*)d_in[8];
    const float* gm = (const float*)d_in[9];
    float* out = (float*)d_out;

    k_pack<<<(MCONV * CIN + 255) / 256, 256>>>(qw, qb, kw, kb, vw, vb);
    k_conv_mma<<<dim3(HW / 128, MCONV / 64, BATCH), 256>>>(x);
    k_pool<<<(BATCH * (C8 + C2) * DOWN + 255) / 256, 256>>>();
    k_attn<<<dim3(DOWN / 128, HW / 64, BATCH), 256>>>();
    k_stats1<<<dim3(DOWN / 256, NCHUNK, BATCH), 256>>>();
    k_stats2<<<dim3(DOWN / 256, BATCH), 256>>>();
    k_apply_mma<<<dim3(HW / 128, BATCH), 256>>>();
    k_out_mma<<<dim3(HW / 128, 256 / 64, BATCH), 256>>>(w2, b2, gm, x, out);
}